// round 1
// baseline (speedup 1.0000x reference)
#include <cuda_runtime.h>
#include <math.h>

#define HH 512
#define WW 512
#define BN 32
#define CN 3

// Scratch (allocation-free rule: __device__ globals)
__device__ float g_Minv[BN * 9];
__device__ float g_A[HH * WW];          // L * 0.85
__device__ float g_Z[CN * HH * WW];     // min(z1,z2) * 0.15

// ---------------------------------------------------------------------------
// Kernel 1: per-batch homography solve (8x8 DLT, partial pivoting, fp64) and
// 3x3 inverse. 32 threads, one per batch.
// ---------------------------------------------------------------------------
__global__ void solve_kernel(const float* __restrict__ dst_off) {
    int b = threadIdx.x;
    if (b >= BN) return;

    const double srcx[4] = {0.0, 511.0, 511.0, 0.0};
    const double srcy[4] = {0.0, 0.0, 511.0, 511.0};
    const double bu[4]   = {0.0, 512.0, 512.0, 0.0};
    const double bv[4]   = {0.0, 0.0, 512.0, 512.0};

    double u[4], v[4];
    #pragma unroll
    for (int i = 0; i < 4; i++) {
        u[i] = bu[i] + (double)dst_off[(b * 4 + i) * 2 + 0];
        v[i] = bv[i] + (double)dst_off[(b * 4 + i) * 2 + 1];
    }

    double A[8][9];  // augmented [A | rhs]
    for (int i = 0; i < 4; i++) {
        double x = srcx[i], y = srcy[i];
        double r1[9] = {x, y, 1.0, 0.0, 0.0, 0.0, -x * u[i], -y * u[i], u[i]};
        double r2[9] = {0.0, 0.0, 0.0, x, y, 1.0, -x * v[i], -y * v[i], v[i]};
        for (int j = 0; j < 9; j++) { A[i][j] = r1[j]; A[i + 4][j] = r2[j]; }
    }

    // Gaussian elimination with partial pivoting
    for (int k = 0; k < 8; k++) {
        int piv = k;
        double mx = fabs(A[k][k]);
        for (int r = k + 1; r < 8; r++) {
            double av = fabs(A[r][k]);
            if (av > mx) { mx = av; piv = r; }
        }
        if (piv != k)
            for (int j = k; j < 9; j++) { double t = A[k][j]; A[k][j] = A[piv][j]; A[piv][j] = t; }
        double inv = 1.0 / A[k][k];
        for (int r = k + 1; r < 8; r++) {
            double f = A[r][k] * inv;
            for (int j = k; j < 9; j++) A[r][j] -= f * A[k][j];
        }
    }
    double p[8];
    for (int k = 7; k >= 0; k--) {
        double s = A[k][8];
        for (int j = k + 1; j < 8; j++) s -= A[k][j] * p[j];
        p[k] = s / A[k][k];
    }

    double m[9] = {p[0], p[1], p[2], p[3], p[4], p[5], p[6], p[7], 1.0};
    double det = m[0] * (m[4] * m[8] - m[5] * m[7])
               - m[1] * (m[3] * m[8] - m[5] * m[6])
               + m[2] * (m[3] * m[7] - m[4] * m[6]);
    double id = 1.0 / det;

    float* o = g_Minv + b * 9;
    o[0] = (float)( (m[4] * m[8] - m[5] * m[7]) * id);
    o[1] = (float)(-(m[1] * m[8] - m[2] * m[7]) * id);
    o[2] = (float)( (m[1] * m[5] - m[2] * m[4]) * id);
    o[3] = (float)(-(m[3] * m[8] - m[5] * m[6]) * id);
    o[4] = (float)( (m[0] * m[8] - m[2] * m[6]) * id);
    o[5] = (float)(-(m[0] * m[5] - m[2] * m[3]) * id);
    o[6] = (float)( (m[3] * m[7] - m[4] * m[6]) * id);
    o[7] = (float)(-(m[0] * m[7] - m[1] * m[6]) * id);
    o[8] = (float)( (m[0] * m[4] - m[1] * m[3]) * id);
}

// ---------------------------------------------------------------------------
// Kernel 2: precompute light mask (x0.85) and moire (x0.15) — batch-invariant.
// ---------------------------------------------------------------------------
__global__ void prep_kernel(const float* __restrict__ ab,
                            const float* __restrict__ centers,
                            const int* __restrict__ cflag,
                            const int* __restrict__ direction,
                            const int* __restrict__ light_xy,
                            const int* __restrict__ theta) {
    int idx = blockIdx.x * blockDim.x + threadIdx.x;
    if (idx >= HH * WW) return;
    int i = idx / WW;   // row
    int j = idx % WW;   // col

    float a = ab[0], bb = ab[1];
    float L;
    if (cflag[0] == 0) {
        int k = direction[0] - 1;  // {0,1,2,3} rot90 count
        int t = (k == 0) ? i : (k == 1) ? j : (k == 2) ? (HH - 1 - i) : (WW - 1 - j);
        L = -((bb - a) / (float)(HH - 1)) * ((float)t - (float)WW) + a;
    } else {
        float x = (float)light_xy[0], y = (float)light_xy[1];
        float d0 = sqrtf(x * x + y * y);
        float d1 = sqrtf((x - 255.f) * (x - 255.f) + y * y);
        float d2 = sqrtf(x * x + (y - 255.f) * (y - 255.f));
        float d3 = sqrtf((x - 512.f) * (x - 512.f) + (y - 512.f) * (y - 512.f));
        float ml = fmaxf(fmaxf(d0, d1), fmaxf(d2, d3));
        float dx = (float)i - x, dy = (float)j - y;
        float dist = sqrtf(dx * dx + dy * dy);
        L = dist / ml * (a - bb) + bb;
    }
    g_A[idx] = L * 0.85f;

    const float TWO_PI = 6.283185307179586f;
    float xg = (float)(i + 1), yg = (float)(j + 1);
    #pragma unroll
    for (int k = 0; k < 3; k++) {
        float cx = centers[k * 2 + 0], cy = centers[k * 2 + 1];
        float th = (float)theta[k] * 0.017453292519943295f;
        float dx = xg - cx, dy = yg - cy;
        float dist = sqrtf(dx * dx + dy * dy);
        float z1 = 0.5f + 0.5f * cosf(TWO_PI * dist);
        float z2 = 0.5f + 0.5f * cosf(TWO_PI * (cosf(th) * xg + sinf(th) * yg));
        // ((min+1)/2)*2 - 1 == min (up to 1ulp) ; fold the 0.15 blend weight
        g_Z[k * (HH * WW) + idx] = fminf(z1, z2) * 0.15f;
    }
}

// ---------------------------------------------------------------------------
// Kernel 3: fused warp + blend. 1 thread = 4 consecutive x pixels, 3 channels.
// Grid: (1, 512, 32), block 128.
// ---------------------------------------------------------------------------
__global__ void __launch_bounds__(128) main_kernel(const float* __restrict__ img,
                                                   const float* __restrict__ noise,
                                                   float* __restrict__ out) {
    int b = blockIdx.z;
    int y = blockIdx.y;
    int x0 = threadIdx.x * 4;

    const float* Mi = g_Minv + b * 9;
    float m00 = Mi[0], m01 = Mi[1], m02 = Mi[2];
    float m10 = Mi[3], m11 = Mi[4], m12 = Mi[5];
    float m20 = Mi[6], m21 = Mi[7], m22 = Mi[8];
    float fy = (float)y;

    float res[3][4];
    float4 Av = *(const float4*)(g_A + y * WW + x0);
    float Aa[4] = {Av.x, Av.y, Av.z, Av.w};

    #pragma unroll
    for (int p = 0; p < 4; p++) {
        float fx = (float)(x0 + p);
        float den = m20 * fx + m21 * fy + m22;
        float inv = 1.0f / den;
        float xs = (m00 * fx + m01 * fy + m02) * inv;
        float ys = (m10 * fx + m11 * fy + m12) * inv;
        float xf = floorf(xs), yf = floorf(ys);
        float wx = xs - xf, wy = ys - yf;
        int ix = (int)xf, iy = (int)yf;
        bool vx0 = (ix >= 0) && (ix < WW);
        bool vx1 = (ix + 1 >= 0) && (ix + 1 < WW);
        bool vy0 = (iy >= 0) && (iy < HH);
        bool vy1 = (iy + 1 >= 0) && (iy + 1 < HH);
        int cx0 = min(max(ix, 0), WW - 1), cx1 = min(max(ix + 1, 0), WW - 1);
        int cy0 = min(max(iy, 0), HH - 1), cy1 = min(max(iy + 1, 0), HH - 1);
        float w00 = (1.f - wx) * (1.f - wy);
        float w01 = wx * (1.f - wy);
        float w10 = (1.f - wx) * wy;
        float w11 = wx * wy;
        #pragma unroll
        for (int ch = 0; ch < 3; ch++) {
            const float* base = img + (size_t)(b * 3 + ch) * (HH * WW);
            float v00 = (vx0 && vy0) ? __ldg(base + cy0 * WW + cx0) : 0.f;
            float v01 = (vx1 && vy0) ? __ldg(base + cy0 * WW + cx1) : 0.f;
            float v10 = (vx0 && vy1) ? __ldg(base + cy1 * WW + cx0) : 0.f;
            float v11 = (vx1 && vy1) ? __ldg(base + cy1 * WW + cx1) : 0.f;
            res[ch][p] = v00 * w00 + v01 * w01 + v10 * w10 + v11 * w11;
        }
    }

    const float kn = 0.031622776601683794f;  // sqrt(0.001)
    #pragma unroll
    for (int ch = 0; ch < 3; ch++) {
        size_t off = ((size_t)(b * 3 + ch) * HH + y) * WW + x0;
        float4 nv = *(const float4*)(noise + off);
        float4 zv = *(const float4*)(g_Z + (ch * HH + y) * WW + x0);
        float4 ov;
        ov.x = res[ch][0] * Aa[0] + zv.x + kn * nv.x;
        ov.y = res[ch][1] * Aa[1] + zv.y + kn * nv.y;
        ov.z = res[ch][2] * Aa[2] + zv.z + kn * nv.z;
        ov.w = res[ch][3] * Aa[3] + zv.w + kn * nv.w;
        *(float4*)(out + off) = ov;
    }
}

// ---------------------------------------------------------------------------
extern "C" void kernel_launch(void* const* d_in, const int* in_sizes, int n_in,
                              void* d_out, int out_size) {
    const float* image    = (const float*)d_in[0];
    const float* dst_off  = (const float*)d_in[1];
    const float* ab       = (const float*)d_in[2];
    const float* centers  = (const float*)d_in[3];
    const float* noise    = (const float*)d_in[4];
    const int*   c        = (const int*)d_in[5];
    const int*   direction= (const int*)d_in[6];
    const int*   light_xy = (const int*)d_in[7];
    const int*   theta    = (const int*)d_in[8];
    float* out = (float*)d_out;

    solve_kernel<<<1, 32>>>(dst_off);
    prep_kernel<<<(HH * WW + 255) / 256, 256>>>(ab, centers, c, direction, light_xy, theta);
    dim3 grid(1, HH, BN);
    main_kernel<<<grid, 128>>>(image, noise, out);
}

// round 2
// speedup vs baseline: 1.2788x; 1.2788x over previous
#include <cuda_runtime.h>
#include <math.h>

#define HH 512
#define WW 512
#define BN 32
#define CN 3

// Scratch (allocation-free rule: __device__ globals)
__device__ float g_Minv[BN * 9];
__device__ float g_A[HH * WW];          // L * 0.85
__device__ float g_Z[CN * HH * WW];     // min(z1,z2) * 0.15

// ---------------------------------------------------------------------------
// Closed-form homography (Heckbert square->quad) + 3x3 inverse, fp64.
// One thread per batch. Algebraically identical to the DLT solve: the 8x8
// system has a unique solution and this is it.
// ---------------------------------------------------------------------------
__device__ __forceinline__ void solve_one(int b, const float* __restrict__ dst_off) {
    const double bu[4] = {0.0, 512.0, 512.0, 0.0};
    const double bv[4] = {0.0, 0.0, 512.0, 512.0};
    double u[4], v[4];
    #pragma unroll
    for (int i = 0; i < 4; i++) {
        u[i] = bu[i] + (double)dst_off[(b * 4 + i) * 2 + 0];
        v[i] = bv[i] + (double)dst_off[(b * 4 + i) * 2 + 1];
    }
    // Unit square (0,0),(1,0),(1,1),(0,1) -> (u0,v0),(u1,v1),(u2,v2),(u3,v3)
    double sx  = u[0] - u[1] + u[2] - u[3];
    double sy  = v[0] - v[1] + v[2] - v[3];
    double dx1 = u[1] - u[2], dx2 = u[3] - u[2];
    double dy1 = v[1] - v[2], dy2 = v[3] - v[2];
    double den = dx1 * dy2 - dx2 * dy1;
    double g = (sx * dy2 - dx2 * sy) / den;
    double h = (dx1 * sy - sx * dy1) / den;
    double a = u[1] - u[0] + g * u[1];
    double bb = u[3] - u[0] + h * u[3];
    double c = u[0];
    double d = v[1] - v[0] + g * v[1];
    double e = v[3] - v[0] + h * v[3];
    double f = v[0];
    // Compose with src scaling (x,y) -> (x/511, y/511): divide first two cols.
    const double is = 1.0 / 511.0;
    double m[9] = {a * is, bb * is, c,
                   d * is, e  * is, f,
                   g * is, h  * is, 1.0};

    double det = m[0] * (m[4] * m[8] - m[5] * m[7])
               - m[1] * (m[3] * m[8] - m[5] * m[6])
               + m[2] * (m[3] * m[7] - m[4] * m[6]);
    double id = 1.0 / det;

    float* o = g_Minv + b * 9;
    o[0] = (float)( (m[4] * m[8] - m[5] * m[7]) * id);
    o[1] = (float)(-(m[1] * m[8] - m[2] * m[7]) * id);
    o[2] = (float)( (m[1] * m[5] - m[2] * m[4]) * id);
    o[3] = (float)(-(m[3] * m[8] - m[5] * m[6]) * id);
    o[4] = (float)( (m[0] * m[8] - m[2] * m[6]) * id);
    o[5] = (float)(-(m[0] * m[5] - m[2] * m[3]) * id);
    o[6] = (float)( (m[3] * m[7] - m[4] * m[6]) * id);
    o[7] = (float)(-(m[0] * m[7] - m[1] * m[6]) * id);
    o[8] = (float)( (m[0] * m[4] - m[1] * m[3]) * id);
}

// ---------------------------------------------------------------------------
// Fused setup: blocks [0,1024) compute light mask (x0.85) + moire (x0.15);
// the last block does the 32 per-batch homography inversions (hidden under
// the prep work, which is far larger).
// ---------------------------------------------------------------------------
__global__ void setup_kernel(const float* __restrict__ dst_off,
                             const float* __restrict__ ab,
                             const float* __restrict__ centers,
                             const int* __restrict__ cflag,
                             const int* __restrict__ direction,
                             const int* __restrict__ light_xy,
                             const int* __restrict__ theta) {
    if (blockIdx.x == gridDim.x - 1) {
        int b = threadIdx.x;
        if (b < BN) solve_one(b, dst_off);
        return;
    }
    int idx = blockIdx.x * blockDim.x + threadIdx.x;
    int i = idx / WW;   // row
    int j = idx % WW;   // col

    float a = ab[0], bb = ab[1];
    float L;
    if (cflag[0] == 0) {
        int k = direction[0] - 1;  // rot90 count {0,1,2,3}
        int t = (k == 0) ? i : (k == 1) ? j : (k == 2) ? (HH - 1 - i) : (WW - 1 - j);
        L = -((bb - a) / (float)(HH - 1)) * ((float)t - (float)WW) + a;
    } else {
        float x = (float)light_xy[0], y = (float)light_xy[1];
        float d0 = sqrtf(x * x + y * y);
        float d1 = sqrtf((x - 255.f) * (x - 255.f) + y * y);
        float d2 = sqrtf(x * x + (y - 255.f) * (y - 255.f));
        float d3 = sqrtf((x - 512.f) * (x - 512.f) + (y - 512.f) * (y - 512.f));
        float ml = fmaxf(fmaxf(d0, d1), fmaxf(d2, d3));
        float dx = (float)i - x, dy = (float)j - y;
        float dist = sqrtf(dx * dx + dy * dy);
        L = dist / ml * (a - bb) + bb;
    }
    g_A[idx] = L * 0.85f;

    const float TWO_PI = 6.283185307179586f;
    float xg = (float)(i + 1), yg = (float)(j + 1);
    #pragma unroll
    for (int k = 0; k < 3; k++) {
        float cx = centers[k * 2 + 0], cy = centers[k * 2 + 1];
        float th = (float)theta[k] * 0.017453292519943295f;
        float dx = xg - cx, dy = yg - cy;
        float dist = sqrtf(dx * dx + dy * dy);
        float z1 = 0.5f + 0.5f * cosf(TWO_PI * dist);
        float z2 = 0.5f + 0.5f * cosf(TWO_PI * (cosf(th) * xg + sinf(th) * yg));
        // ((min+1)/2)*2 - 1 == min ; fold the 0.15 blend weight
        g_Z[k * (HH * WW) + idx] = fminf(z1, z2) * 0.15f;
    }
}

// ---------------------------------------------------------------------------
// Fused warp + blend. 1 thread = 4 consecutive x pixels, 3 channels.
// Grid: (1, 512, 32), block 128.
// ---------------------------------------------------------------------------
__global__ void __launch_bounds__(128) main_kernel(const float* __restrict__ img,
                                                   const float* __restrict__ noise,
                                                   float* __restrict__ out) {
    int b = blockIdx.z;
    int y = blockIdx.y;
    int x0 = threadIdx.x * 4;

    const float* Mi = g_Minv + b * 9;
    float m00 = Mi[0], m01 = Mi[1], m02 = Mi[2];
    float m10 = Mi[3], m11 = Mi[4], m12 = Mi[5];
    float m20 = Mi[6], m21 = Mi[7], m22 = Mi[8];
    float fy = (float)y;

    float res[3][4];
    float4 Av = *(const float4*)(g_A + y * WW + x0);
    float Aa[4] = {Av.x, Av.y, Av.z, Av.w};

    #pragma unroll
    for (int p = 0; p < 4; p++) {
        float fx = (float)(x0 + p);
        float den = m20 * fx + m21 * fy + m22;
        float inv = 1.0f / den;
        float xs = (m00 * fx + m01 * fy + m02) * inv;
        float ys = (m10 * fx + m11 * fy + m12) * inv;
        float xf = floorf(xs), yf = floorf(ys);
        float wx = xs - xf, wy = ys - yf;
        int ix = (int)xf, iy = (int)yf;
        bool vx0 = (ix >= 0) && (ix < WW);
        bool vx1 = (ix + 1 >= 0) && (ix + 1 < WW);
        bool vy0 = (iy >= 0) && (iy < HH);
        bool vy1 = (iy + 1 >= 0) && (iy + 1 < HH);
        int cx0 = min(max(ix, 0), WW - 1), cx1 = min(max(ix + 1, 0), WW - 1);
        int cy0 = min(max(iy, 0), HH - 1), cy1 = min(max(iy + 1, 0), HH - 1);
        float w00 = (1.f - wx) * (1.f - wy);
        float w01 = wx * (1.f - wy);
        float w10 = (1.f - wx) * wy;
        float w11 = wx * wy;
        #pragma unroll
        for (int ch = 0; ch < 3; ch++) {
            const float* base = img + (size_t)(b * 3 + ch) * (HH * WW);
            float v00 = (vx0 && vy0) ? __ldg(base + cy0 * WW + cx0) : 0.f;
            float v01 = (vx1 && vy0) ? __ldg(base + cy0 * WW + cx1) : 0.f;
            float v10 = (vx0 && vy1) ? __ldg(base + cy1 * WW + cx0) : 0.f;
            float v11 = (vx1 && vy1) ? __ldg(base + cy1 * WW + cx1) : 0.f;
            res[ch][p] = v00 * w00 + v01 * w01 + v10 * w10 + v11 * w11;
        }
    }

    const float kn = 0.031622776601683794f;  // sqrt(0.001)
    #pragma unroll
    for (int ch = 0; ch < 3; ch++) {
        size_t off = ((size_t)(b * 3 + ch) * HH + y) * WW + x0;
        float4 nv = *(const float4*)(noise + off);
        float4 zv = *(const float4*)(g_Z + (ch * HH + y) * WW + x0);
        float4 ov;
        ov.x = res[ch][0] * Aa[0] + zv.x + kn * nv.x;
        ov.y = res[ch][1] * Aa[1] + zv.y + kn * nv.y;
        ov.z = res[ch][2] * Aa[2] + zv.z + kn * nv.z;
        ov.w = res[ch][3] * Aa[3] + zv.w + kn * nv.w;
        *(float4*)(out + off) = ov;
    }
}

// ---------------------------------------------------------------------------
extern "C" void kernel_launch(void* const* d_in, const int* in_sizes, int n_in,
                              void* d_out, int out_size) {
    const float* image    = (const float*)d_in[0];
    const float* dst_off  = (const float*)d_in[1];
    const float* ab       = (const float*)d_in[2];
    const float* centers  = (const float*)d_in[3];
    const float* noise    = (const float*)d_in[4];
    const int*   c        = (const int*)d_in[5];
    const int*   direction= (const int*)d_in[6];
    const int*   light_xy = (const int*)d_in[7];
    const int*   theta    = (const int*)d_in[8];
    float* out = (float*)d_out;

    // 1024 prep blocks (512*512/256) + 1 solve block
    setup_kernel<<<(HH * WW) / 256 + 1, 256>>>(dst_off, ab, centers, c,
                                               direction, light_xy, theta);
    dim3 grid(1, HH, BN);
    main_kernel<<<grid, 128>>>(image, noise, out);
}